// round 3
// baseline (speedup 1.0000x reference)
#include <cuda_runtime.h>
#include <cuda_bf16.h>

// Shapes (fixed):
//   query_times [B,P,LE], event_times [B,P,L] (sorted),
//   mu/alpha/beta [B,M,P,L], out [B,M,P,LE] fp32
constexpr int B  = 8;
constexpr int P  = 16;
constexpr int L  = 256;
constexpr int M  = 16;
constexpr int LE = 2048;

constexpr int NT      = 512;          // threads per block
constexpr int QPB     = 1024;         // queries per block (LE split in 2 chunks)
constexpr int LPAD    = 17;           // padded ci stride (bank-conflict-free)
// smem float offsets
constexpr int OFF_EV   = 0;                         // sev[256]
constexpr int OFF_MU   = OFF_EV + L;                // smu[256*17]
constexpr int OFF_AL   = OFF_MU + L * LPAD;
constexpr int OFF_BE   = OFF_AL + L * LPAD;
constexpr int OFF_CIDT = OFF_BE + L * LPAD;         // float2[1024] -> 2048 floats
constexpr int OFF_OUT  = OFF_CIDT + 2 * QPB;        // sout[16][257]
constexpr int SMEM_FLOATS = OFF_OUT + M * 257;
constexpr int SMEM_BYTES  = SMEM_FLOATS * 4;        // ~77.9 KB

// softplus(x) on x in (0,1): degree-6 Taylor at 0.5 (max err ~6e-7 abs)
__device__ __forceinline__ float softplus01(float x) {
    const float y = x - 0.5f;
    float r = 0.00018836f;
    r = fmaf(r, y, 0.00087297f);
    r = fmaf(r, y, -0.00401486f);
    r = fmaf(r, y, -0.00959280f);
    r = fmaf(r, y, 0.11750186f);
    r = fmaf(r, y, 0.62245933f);
    r = fmaf(r, y, 0.97407698f);
    return r;
}

__global__ __launch_bounds__(NT, 2)
void hawkes_kernel(const float* __restrict__ q,
                   const float* __restrict__ ev,
                   const float* __restrict__ mu,
                   const float* __restrict__ al,
                   const float* __restrict__ be,
                   float* __restrict__ out)
{
    extern __shared__ float sm[];
    float*  sev   = sm + OFF_EV;
    float*  smu   = sm + OFF_MU;
    float*  sal   = sm + OFF_AL;
    float*  sbe   = sm + OFF_BE;
    float2* scidt = (float2*)(sm + OFF_CIDT);
    float*  sout  = sm + OFF_OUT;

    const int tid   = threadIdx.x;
    const int chunk = blockIdx.x & 1;        // which half of LE
    const int bp    = blockIdx.x >> 1;       // b*P + p
    const int p     = bp & (P - 1);
    const int b     = bp >> 4;

    // ---- Stage: events + params ([ci*17 + m] layout; STS stride 17 -> conflict-free)
    if (tid < L) sev[tid] = ev[bp * L + tid];
    #pragma unroll
    for (int i = tid; i < M * L; i += NT) {          // 8 iters, coalesced LDG
        const int m  = i >> 8;
        const int ci = i & (L - 1);
        const int g  = ((b * M + m) * P + p) * L + ci;
        const int s  = ci * LPAD + m;
        smu[s] = mu[g];
        sal[s] = al[g];
        sbe[s] = be[g];
    }
    __syncthreads();

    // ---- Phase 1: binary search, 2 queries per thread, park (dt, ci)
    #pragma unroll
    for (int k = 0; k < 2; ++k) {
        const int   ql = k * NT + tid;               // 0..1023
        const float qt = q[bp * LE + chunk * QPB + ql];
        int lo = 0, hi = L;
        #pragma unroll
        for (int it = 0; it < 9; ++it) {
            if (lo < hi) {
                const int mid = (lo + hi) >> 1;
                if (sev[mid] < qt) lo = mid + 1; else hi = mid;
            }
        }
        const int   last = lo - 1;
        const int   ci   = (last < 0) ? 0   : last;
        const float tl   = (last < 0) ? 0.f : sev[ci];
        scidt[ql] = make_float2(qt - tl, __int_as_float(ci));
    }
    __syncthreads();

    // ---- Phase 2: lane<->m mapping. Warp = 2 queries x 16 models.
    const int m    = tid & 15;
    const int qsel = tid >> 4;                       // 0..31 (query slot per iteration)
    const size_t obase = ((size_t)(b * M + m) * P + p) * LE + chunk * QPB;

    #pragma unroll 1
    for (int f = 0; f < 4; ++f) {                    // 4 flush chunks of 256 queries
        #pragma unroll 4
        for (int j = 0; j < 8; ++j) {
            const int    ql = (f * 8 + j) * 32 + qsel;
            const float2 cd = scidt[ql];             // broadcast LDS.64
            const float  dt = cd.x;
            const int    ci = __float_as_int(cd.y);
            const int    s  = ci * LPAD + m;
            const float  mm = smu[s];
            const float  aa = sal[s];
            const float  bb = sbe[s];
            const float  c  = dt * -1.44269504f;
            const float  e  = exp2f(bb * c);
            const float  base = fmaf(aa - mm, e, mm);   // in (0,1)
            sout[m * 257 + (j * 32 + qsel)] = softplus01(base);
        }
        __syncthreads();
        // Flush 256 queries x 16 models, coalesced
        #pragma unroll
        for (int j = tid; j < M * 256; j += NT) {
            const int mm2 = j >> 8;
            const int qq  = j & 255;
            out[((size_t)(b * M + mm2) * P + p) * LE + chunk * QPB + f * 256 + qq]
                = sout[mm2 * 257 + qq];
        }
        __syncthreads();
    }
    (void)obase;
}

extern "C" void kernel_launch(void* const* d_in, const int* in_sizes, int n_in,
                              void* d_out, int out_size)
{
    const float* q  = (const float*)d_in[0];
    const float* ev = (const float*)d_in[1];
    const float* mu = (const float*)d_in[2];
    const float* al = (const float*)d_in[3];
    const float* be = (const float*)d_in[4];
    float* out = (float*)d_out;

    static bool attr_set = false;
    if (!attr_set) {
        cudaFuncSetAttribute(hawkes_kernel,
                             cudaFuncAttributeMaxDynamicSharedMemorySize,
                             SMEM_BYTES);
        attr_set = true;
    }
    hawkes_kernel<<<B * P * 2, NT, SMEM_BYTES>>>(q, ev, mu, al, be, out);
}

// round 4
// speedup vs baseline: 1.1604x; 1.1604x over previous
#include <cuda_runtime.h>
#include <cuda_bf16.h>

// Shapes (fixed):
//   query_times [B,P,LE], event_times [B,P,L] (sorted),
//   mu/alpha/beta [B,M,P,L], out [B,M,P,LE] fp32
constexpr int B  = 8;
constexpr int P  = 16;
constexpr int L  = 256;
constexpr int M  = 16;
constexpr int LE = 2048;

constexpr int NT      = 1024;        // one block per (b,p)
constexpr int RSTRIDE = 52;          // floats per ci row: mu16|al16|be16|pad4 (208B)
constexpr int SMEM_FLOATS = L * RSTRIDE + L;     // params + sev
constexpr int SMEM_BYTES  = SMEM_FLOATS * 4;     // 54,272 B

// softplus(x) for x in [0,1): degree-4 Taylor at 0.5, abs err <= ~3e-5
__device__ __forceinline__ float sp01(float x) {
    const float y = x - 0.5f;
    float r = -0.00401486f;
    r = fmaf(r, y, -0.00959280f);
    r = fmaf(r, y,  0.11750186f);
    r = fmaf(r, y,  0.62245933f);
    r = fmaf(r, y,  0.97407698f);
    return r;
}

// branchless lower_bound over sev[0..255]: returns #elements < qt  (0..256)
__device__ __forceinline__ int lb256(const float* __restrict__ sev, float qt) {
    int lo = 0;
    if (sev[lo + 127] < qt) lo += 128;
    if (sev[lo +  63] < qt) lo += 64;
    if (sev[lo +  31] < qt) lo += 32;
    if (sev[lo +  15] < qt) lo += 16;
    if (sev[lo +   7] < qt) lo += 8;
    if (sev[lo +   3] < qt) lo += 4;
    if (sev[lo +   1] < qt) lo += 2;
    if (sev[lo      ] < qt) lo += 1;
    if (lo < L && sev[lo] < qt) lo += 1;   // final width-1 step (257 outcomes)
    return lo;
}

__global__ __launch_bounds__(NT, 1)
void hawkes_kernel(const float* __restrict__ q,
                   const float* __restrict__ ev,
                   const float* __restrict__ mu,
                   const float* __restrict__ al,
                   const float* __restrict__ be,
                   float* __restrict__ out)
{
    extern __shared__ float sm[];
    float* spar = sm;                 // [L][RSTRIDE]
    float* sev  = sm + L * RSTRIDE;   // [L]

    const int tid = threadIdx.x;
    const int bp  = blockIdx.x;       // b*P + p
    const int p   = bp & (P - 1);
    const int b   = bp >> 4;

    // ---- Stage events + params (params staged ONCE per (b,p)).
    if (tid < L) sev[tid] = ev[bp * L + tid];
    #pragma unroll
    for (int k = 0; k < 4; ++k) {                 // 4*1024 = 4096 = M*L
        const int i  = k * NT + tid;
        const int m  = i >> 8;                    // 0..15
        const int ci = i & (L - 1);
        const int g  = ((b * M + m) * P + p) * L + ci;
        const int s  = ci * RSTRIDE;
        spar[s +      m] = mu[g];
        spar[s + 16 + m] = al[g];
        spar[s + 32 + m] = be[g];
    }
    __syncthreads();

    // ---- Search: 2 consecutive queries per thread (results stay in regs).
    const float2 qv = *(const float2*)(q + bp * LE + 2 * tid);

    const int lo0 = lb256(sev, qv.x);
    const int lo1 = lb256(sev, qv.y);
    const int ci0 = (lo0 > 0) ? lo0 - 1 : 0;
    const int ci1 = (lo1 > 0) ? lo1 - 1 : 0;
    const float tl0 = (lo0 > 0) ? sev[ci0] : 0.f;
    const float tl1 = (lo1 > 0) ? sev[ci1] : 0.f;
    const float c0 = -1.44269504f * (qv.x - tl0);  // exp(-b*dt) = exp2(b*c)
    const float c1 = -1.44269504f * (qv.y - tl1);

    // ---- Compute: 16 models via 4 float4 gather groups per query.
    const float4* r0 = (const float4*)(spar + ci0 * RSTRIDE);
    const float4* r1 = (const float4*)(spar + ci1 * RSTRIDE);
    float2* op = (float2*)(out + ((size_t)(b * M) * P + p) * LE + 2 * tid);
    const size_t ostr2 = (size_t)P * LE / 2;       // m-stride in float2 units

    #pragma unroll
    for (int g = 0; g < 4; ++g) {
        const float4 m0 = r0[g], a0 = r0[4 + g], b0 = r0[8 + g];
        const float4 m1 = r1[g], a1 = r1[4 + g], b1 = r1[8 + g];

        #define DO_LANE(J, MJ, AJ, BJ)                                          \
        {                                                                       \
            const float e0 = exp2f(b0.BJ * c0);                                 \
            const float e1 = exp2f(b1.BJ * c1);                                 \
            const float s0 = sp01(fmaf(a0.AJ - m0.MJ, e0, m0.MJ));              \
            const float s1 = sp01(fmaf(a1.AJ - m1.MJ, e1, m1.MJ));              \
            op[(size_t)(4 * g + J) * ostr2] = make_float2(s0, s1);              \
        }
        DO_LANE(0, x, x, x)
        DO_LANE(1, y, y, y)
        DO_LANE(2, z, z, z)
        DO_LANE(3, w, w, w)
        #undef DO_LANE
    }
}

extern "C" void kernel_launch(void* const* d_in, const int* in_sizes, int n_in,
                              void* d_out, int out_size)
{
    const float* q  = (const float*)d_in[0];
    const float* ev = (const float*)d_in[1];
    const float* mu = (const float*)d_in[2];
    const float* al = (const float*)d_in[3];
    const float* be = (const float*)d_in[4];
    float* out = (float*)d_out;

    static bool attr_set = false;
    if (!attr_set) {
        cudaFuncSetAttribute(hawkes_kernel,
                             cudaFuncAttributeMaxDynamicSharedMemorySize,
                             SMEM_BYTES);
        attr_set = true;
    }
    hawkes_kernel<<<B * P, NT, SMEM_BYTES>>>(q, ev, mu, al, be, out);
}